// round 3
// baseline (speedup 1.0000x reference)
#include <cuda_runtime.h>
#include <cuda_bf16.h>
#include <cstdint>

typedef __nv_bfloat16 bf16;
typedef __nv_bfloat162 bf162;

#define N_NODES 100000
#define E_EDGES 1600000
#define C_IN 256
#define C_HID 256
#define C_OUT 32

// ---------------- device scratch (static, no allocation) ----------------
__device__ bf16 g_xhi[N_NODES * C_IN];
__device__ bf16 g_xlo[N_NODES * C_IN];
__device__ bf16 g_h1hi[N_NODES * C_HID];
__device__ bf16 g_h1lo[N_NODES * C_HID];
__device__ bf16 g_h2hi[N_NODES * C_HID];
__device__ bf16 g_h2lo[N_NODES * C_HID];
__device__ bf16 g_w1hi[C_IN * C_HID];
__device__ bf16 g_w1lo[C_IN * C_HID];
__device__ bf16 g_w2hi[C_HID * C_HID];
__device__ bf16 g_w2lo[C_HID * C_HID];
__device__ bf16 g_w3hi[C_OUT * C_HID];
__device__ bf16 g_w3lo[C_OUT * C_HID];
__device__ float g_h0[N_NODES * C_OUT];
__device__ float g_hbuf[N_NODES * C_OUT];
__device__ int   g_deg[N_NODES];
__device__ float g_dinv[N_NODES];
__device__ int   g_start[N_NODES + 1];
__device__ int   g_cursor[N_NODES];
__device__ int   g_esrc[E_EDGES];
__device__ float g_ew[E_EDGES];
__device__ int   g_is64;

// ---------------- edge dtype detection ----------------
// int64 values < 2^31: every odd int32 word (high half) is 0.
// int32 data: odd words are random node ids -> essentially never all zero.
__global__ void detect_kernel(const int* __restrict__ ei) {
    int v = ei[2 * threadIdx.x + 1];
    int any = __syncthreads_or(v != 0);
    if (threadIdx.x == 0) g_is64 = (any == 0) ? 1 : 0;
}

// ---------------- splits ----------------
__global__ void split_x_kernel(const float* __restrict__ x) {
    int t = blockIdx.x * blockDim.x + threadIdx.x;
    if (t >= N_NODES * C_IN / 2) return;
    float2 v = *(const float2*)(x + 2 * t);
    bf162 h, l;
    h.x = __float2bfloat16(v.x);
    h.y = __float2bfloat16(v.y);
    l.x = __float2bfloat16(v.x - __bfloat162float(h.x));
    l.y = __float2bfloat16(v.y - __bfloat162float(h.y));
    ((bf162*)g_xhi)[t] = h;
    ((bf162*)g_xlo)[t] = l;
}

// splits weight W[k][n] (row-major K x Nn) into transposed bf16 hi/lo [n][K]
__global__ void split_w_kernel(int layer, const float* __restrict__ W) {
    const int Kd = 256;
    int Nn;
    bf16 *hi, *lo;
    if (layer == 0)      { Nn = 256; hi = g_w1hi; lo = g_w1lo; }
    else if (layer == 1) { Nn = 256; hi = g_w2hi; lo = g_w2lo; }
    else                 { Nn = 32;  hi = g_w3hi; lo = g_w3lo; }
    int idx = blockIdx.x * blockDim.x + threadIdx.x;
    if (idx >= Kd * Nn) return;
    int k = idx / Nn, n = idx % Nn;
    float v = W[idx];
    bf16 h = __float2bfloat16(v);
    hi[n * Kd + k] = h;
    lo[n * Kd + k] = __float2bfloat16(v - __bfloat162float(h));
}

// ---------------- bf16x3 tensor-core GEMM ----------------
__device__ __forceinline__ void mma16816(float* c, const uint32_t* a, const uint32_t* b) {
    asm volatile(
        "mma.sync.aligned.m16n8k16.row.col.f32.bf16.bf16.f32 "
        "{%0,%1,%2,%3}, {%4,%5,%6,%7}, {%8,%9}, {%0,%1,%2,%3};\n"
        : "+f"(c[0]), "+f"(c[1]), "+f"(c[2]), "+f"(c[3])
        : "r"(a[0]), "r"(a[1]), "r"(a[2]), "r"(a[3]), "r"(b[0]), "r"(b[1]));
}

// C[M,Nn] = A[M,256] * B[256,Nn] (+bias, optional relu)
// A given as hi/lo bf16 row-major; B given as hi/lo bf16 TRANSPOSED [n][256].
// Computes A_hi*B_hi + A_lo*B_hi + A_hi*B_lo (3 K-segments of 256).
// Block tile 128x64, KC=64, 4 warps, warp tile 64x32.
template <bool RELU, bool SPLIT>
__global__ void __launch_bounds__(128) gemm_kernel(int layer,
                                                   const float* __restrict__ bias,
                                                   int M, int Nn) {
    const bf16 *Ahi, *Alo, *Bhi, *Blo;
    bf16 *Ohi = nullptr, *Olo = nullptr;
    float* Of = nullptr;
    if (layer == 0)      { Ahi = g_xhi;  Alo = g_xlo;  Bhi = g_w1hi; Blo = g_w1lo; Ohi = g_h1hi; Olo = g_h1lo; }
    else if (layer == 1) { Ahi = g_h1hi; Alo = g_h1lo; Bhi = g_w2hi; Blo = g_w2lo; Ohi = g_h2hi; Olo = g_h2lo; }
    else                 { Ahi = g_h2hi; Alo = g_h2lo; Bhi = g_w3hi; Blo = g_w3lo; Of = g_h0; }

    __shared__ bf16 As[128][72];  // row stride 72 bf16 = 144B -> conflict-free frag loads
    __shared__ bf16 Bs[64][72];

    const int m0 = blockIdx.x * 128;
    const int n0 = blockIdx.y * 64;
    const int tid = threadIdx.x;
    const int warp = tid >> 5, lane = tid & 31;
    const int g = lane >> 2, tg = lane & 3;
    const int wrow = (warp >> 1) * 64, wcol = (warp & 1) * 32;

    float acc[4][4][4];
#pragma unroll
    for (int a = 0; a < 4; a++)
#pragma unroll
        for (int b = 0; b < 4; b++)
#pragma unroll
            for (int c = 0; c < 4; c++) acc[a][b][c] = 0.f;

#pragma unroll 1
    for (int seg = 0; seg < 3; ++seg) {
        const bf16* Ap = (seg == 1) ? Alo : Ahi;
        const bf16* Bp = (seg == 2) ? Blo : Bhi;
#pragma unroll 1
        for (int kc = 0; kc < 256; kc += 64) {
            __syncthreads();
            // load A tile 128x64 (16B per chunk, 8 chunks/thread)
#pragma unroll
            for (int i = 0; i < 8; i++) {
                int id = i * 128 + tid;
                int r = id >> 3, c8 = (id & 7) << 3;
                uint4 v = make_uint4(0u, 0u, 0u, 0u);
                int row = m0 + r;
                if (row < M) v = *(const uint4*)(Ap + (size_t)row * 256 + kc + c8);
                *(uint4*)(&As[r][c8]) = v;
            }
            // load B tile 64x64 (transposed weights: rows = n)
#pragma unroll
            for (int i = 0; i < 4; i++) {
                int id = i * 128 + tid;
                int r = id >> 3, c8 = (id & 7) << 3;
                uint4 v = make_uint4(0u, 0u, 0u, 0u);
                if (n0 + r < Nn) v = *(const uint4*)(Bp + (size_t)(n0 + r) * 256 + kc + c8);
                *(uint4*)(&Bs[r][c8]) = v;
            }
            __syncthreads();
#pragma unroll
            for (int ks = 0; ks < 64; ks += 16) {
                uint32_t afr[4][4], bfr[4][2];
#pragma unroll
                for (int mt = 0; mt < 4; mt++) {
                    int rb = wrow + mt * 16;
                    afr[mt][0] = *(const uint32_t*)(&As[rb + g][ks + 2 * tg]);
                    afr[mt][1] = *(const uint32_t*)(&As[rb + g + 8][ks + 2 * tg]);
                    afr[mt][2] = *(const uint32_t*)(&As[rb + g][ks + 2 * tg + 8]);
                    afr[mt][3] = *(const uint32_t*)(&As[rb + g + 8][ks + 2 * tg + 8]);
                }
#pragma unroll
                for (int nt = 0; nt < 4; nt++) {
                    int cb = wcol + nt * 8 + g;
                    bfr[nt][0] = *(const uint32_t*)(&Bs[cb][ks + 2 * tg]);
                    bfr[nt][1] = *(const uint32_t*)(&Bs[cb][ks + 2 * tg + 8]);
                }
#pragma unroll
                for (int mt = 0; mt < 4; mt++)
#pragma unroll
                    for (int nt = 0; nt < 4; nt++)
                        mma16816(acc[mt][nt], afr[mt], bfr[nt]);
            }
        }
    }

    // epilogue: bias (+relu), write split bf16 activations or fp32 h0
#pragma unroll
    for (int mt = 0; mt < 4; mt++) {
        int r0 = m0 + wrow + mt * 16 + g;
#pragma unroll
        for (int nt = 0; nt < 4; nt++) {
            int c0 = n0 + wcol + nt * 8 + 2 * tg;
            if (c0 >= Nn) continue;
            float b0v = bias[c0], b1v = bias[c0 + 1];
            float v00 = acc[mt][nt][0] + b0v;
            float v01 = acc[mt][nt][1] + b1v;
            float v10 = acc[mt][nt][2] + b0v;
            float v11 = acc[mt][nt][3] + b1v;
            if (RELU) {
                v00 = fmaxf(v00, 0.f); v01 = fmaxf(v01, 0.f);
                v10 = fmaxf(v10, 0.f); v11 = fmaxf(v11, 0.f);
            }
            if (SPLIT) {
                if (r0 < M) {
                    bf162 h, l;
                    h.x = __float2bfloat16(v00); h.y = __float2bfloat16(v01);
                    l.x = __float2bfloat16(v00 - __bfloat162float(h.x));
                    l.y = __float2bfloat16(v01 - __bfloat162float(h.y));
                    *(bf162*)(Ohi + (size_t)r0 * Nn + c0) = h;
                    *(bf162*)(Olo + (size_t)r0 * Nn + c0) = l;
                }
                if (r0 + 8 < M) {
                    bf162 h, l;
                    h.x = __float2bfloat16(v10); h.y = __float2bfloat16(v11);
                    l.x = __float2bfloat16(v10 - __bfloat162float(h.x));
                    l.y = __float2bfloat16(v11 - __bfloat162float(h.y));
                    *(bf162*)(Ohi + (size_t)(r0 + 8) * Nn + c0) = h;
                    *(bf162*)(Olo + (size_t)(r0 + 8) * Nn + c0) = l;
                }
            } else {
                if (r0 < M)     *(float2*)(Of + (size_t)r0 * Nn + c0) = make_float2(v00, v01);
                if (r0 + 8 < M) *(float2*)(Of + (size_t)(r0 + 8) * Nn + c0) = make_float2(v10, v11);
            }
        }
    }
}

// ---------------- graph normalization + CSR build ----------------
__global__ void deg_init_kernel() {
    int i = blockIdx.x * blockDim.x + threadIdx.x;
    if (i < N_NODES) { g_deg[i] = 1; g_cursor[i] = 0; }  // self-loop included
}

__global__ void deg_count_kernel(const void* __restrict__ ei) {
    int e = blockIdx.x * blockDim.x + threadIdx.x;
    if (e >= E_EDGES) return;
    int d;
    if (g_is64) d = (int)((const long long*)ei)[E_EDGES + e];
    else        d = ((const int*)ei)[E_EDGES + e];
    atomicAdd(&g_deg[d], 1);
}

__global__ void dinv_kernel() {
    int i = blockIdx.x * blockDim.x + threadIdx.x;
    if (i < N_NODES) g_dinv[i] = rsqrtf((float)g_deg[i]);  // deg >= 1 always
}

// single-block exclusive scan of (deg[i]-1) -> g_start
__global__ void scan_kernel() {
    __shared__ int ssum[1024];
    const int t = threadIdx.x;
    const int CH = (N_NODES + 1023) / 1024;  // 98
    int begin = t * CH;
    int end = begin + CH; if (end > N_NODES) end = N_NODES;
    int s = 0;
    for (int i = begin; i < end && i < N_NODES; i++) s += g_deg[i] - 1;
    ssum[t] = s;
    __syncthreads();
    for (int off = 1; off < 1024; off <<= 1) {
        int v = (t >= off) ? ssum[t - off] : 0;
        __syncthreads();
        ssum[t] += v;
        __syncthreads();
    }
    int run = (t == 0) ? 0 : ssum[t - 1];
    for (int i = begin; i < end && i < N_NODES; i++) {
        g_start[i] = run;
        run += g_deg[i] - 1;
    }
    if (t == 1023) g_start[N_NODES] = run;  // == E_EDGES
}

__global__ void scatter_kernel(const void* __restrict__ ei) {
    int e = blockIdx.x * blockDim.x + threadIdx.x;
    if (e >= E_EDGES) return;
    int s, d;
    if (g_is64) {
        const long long* p = (const long long*)ei;
        s = (int)p[e]; d = (int)p[E_EDGES + e];
    } else {
        const int* p = (const int*)ei;
        s = p[e]; d = p[E_EDGES + e];
    }
    int pos = g_start[d] + atomicAdd(&g_cursor[d], 1);
    g_esrc[pos] = s;
    g_ew[pos] = g_dinv[s] * g_dinv[d];
}

// ---------------- fused propagation round (gather, no atomics) ----------------
// out = 0.9 * (sum_{e->node} w_e * h[src_e] + dinv^2 * h[node]) + 0.1 * h0[node]
__global__ void prop_kernel(int round, float* __restrict__ dout) {
    const float* hin = (round == 0) ? g_h0 : g_hbuf;
    float* hout = (round == 0) ? g_hbuf : dout;
    int gid = blockIdx.x * blockDim.x + threadIdx.x;
    int node = gid >> 3;
    int sub = gid & 7;
    if (node >= N_NODES) return;
    const float4* hin4 = (const float4*)hin;
    int s = g_start[node];
    int e = g_start[node + 1];
    float4 acc = make_float4(0.f, 0.f, 0.f, 0.f);
    for (int j = s; j < e; j++) {
        int src = g_esrc[j];
        float w = g_ew[j];
        float4 hv = hin4[src * 8 + sub];
        acc.x += w * hv.x; acc.y += w * hv.y;
        acc.z += w * hv.z; acc.w += w * hv.w;
    }
    float di = g_dinv[node];
    float sw = di * di;
    float4 hs = hin4[node * 8 + sub];
    float4 h0v = ((const float4*)g_h0)[node * 8 + sub];
    float4 o;
    o.x = 0.9f * (acc.x + sw * hs.x) + 0.1f * h0v.x;
    o.y = 0.9f * (acc.y + sw * hs.y) + 0.1f * h0v.y;
    o.z = 0.9f * (acc.z + sw * hs.z) + 0.1f * h0v.z;
    o.w = 0.9f * (acc.w + sw * hs.w) + 0.1f * h0v.w;
    ((float4*)hout)[node * 8 + sub] = o;
}

// ---------------- launch ----------------
extern "C" void kernel_launch(void* const* d_in, const int* in_sizes, int n_in,
                              void* d_out, int out_size) {
    const float* x     = (const float*)d_in[0];
    const void*  ei    = d_in[1];
    const float* W_in  = (const float*)d_in[2];
    const float* b_in  = (const float*)d_in[3];
    const float* W_h   = (const float*)d_in[4];
    const float* b_h   = (const float*)d_in[5];
    const float* W_out = (const float*)d_in[6];
    const float* b_out = (const float*)d_in[7];
    float* out = (float*)d_out;

    detect_kernel<<<1, 256>>>((const int*)ei);

    split_x_kernel<<<(N_NODES * C_IN / 2 + 255) / 256, 256>>>(x);
    split_w_kernel<<<(C_IN * C_HID + 255) / 256, 256>>>(0, W_in);
    split_w_kernel<<<(C_HID * C_HID + 255) / 256, 256>>>(1, W_h);
    split_w_kernel<<<(C_HID * C_OUT + 255) / 256, 256>>>(2, W_out);

    const int MB = (N_NODES + 127) / 128;  // 782
    gemm_kernel<true, true><<<dim3(MB, C_HID / 64), 128>>>(0, b_in, N_NODES, C_HID);
    gemm_kernel<true, true><<<dim3(MB, C_HID / 64), 128>>>(1, b_h, N_NODES, C_HID);
    gemm_kernel<false, false><<<dim3(MB, 1), 128>>>(2, b_out, N_NODES, C_OUT);

    deg_init_kernel<<<(N_NODES + 255) / 256, 256>>>();
    deg_count_kernel<<<(E_EDGES + 255) / 256, 256>>>(ei);
    dinv_kernel<<<(N_NODES + 255) / 256, 256>>>();
    scan_kernel<<<1, 1024>>>();
    scatter_kernel<<<(E_EDGES + 255) / 256, 256>>>(ei);

    const int PB = (N_NODES * 8 + 255) / 256;  // 3125
    prop_kernel<<<PB, 256>>>(0, out);
    prop_kernel<<<PB, 256>>>(1, out);
}

// round 9
// speedup vs baseline: 1.1901x; 1.1901x over previous
#include <cuda_runtime.h>
#include <cuda_bf16.h>
#include <cstdint>

typedef __nv_bfloat16 bf16;
typedef __nv_bfloat162 bf162;

#define N_NODES 100000
#define E_EDGES 1600000
#define C_IN 256
#define C_HID 256
#define C_OUT 32

// ---------------- device scratch (static, no allocation) ----------------
// NOTE: these symbols are referenced ONLY inside device code. Passing them as
// kernel arguments from host code silently passes the host shadow address
// (HMM then migrates host pages -> 256MB device delta -> harness violation).
__device__ __align__(16) float g_h1[N_NODES * C_HID];
__device__ __align__(16) float g_h2[N_NODES * C_HID];
__device__ __align__(16) float g_h0[N_NODES * C_OUT];
__device__ __align__(16) float g_hbuf[N_NODES * C_OUT];
__device__ __align__(16) bf16 g_w1hi[C_IN * C_HID];
__device__ __align__(16) bf16 g_w1lo[C_IN * C_HID];
__device__ __align__(16) bf16 g_w2hi[C_HID * C_HID];
__device__ __align__(16) bf16 g_w2lo[C_HID * C_HID];
__device__ __align__(16) bf16 g_w3hi[C_OUT * C_HID];
__device__ __align__(16) bf16 g_w3lo[C_OUT * C_HID];
__device__ int   g_deg[N_NODES];
__device__ float g_dinv[N_NODES];
__device__ int   g_start[N_NODES + 1];
__device__ int   g_cursor[N_NODES];
__device__ int   g_esrc[E_EDGES];
__device__ float g_ew[E_EDGES];
__device__ int   g_is64;

// ---------------- edge dtype detection ----------------
__global__ void detect_kernel(const int* __restrict__ ei) {
    int v = ei[2 * threadIdx.x + 1];
    int any = __syncthreads_or(v != 0);
    if (threadIdx.x == 0) g_is64 = (any == 0) ? 1 : 0;
}

// splits weight W[k][n] (row-major 256 x Nn) into transposed bf16 hi/lo [n][256]
__global__ void split_w_kernel(int layer, const float* __restrict__ W) {
    const int Kd = 256;
    int Nn;
    bf16 *hi, *lo;
    if (layer == 0)      { Nn = 256; hi = g_w1hi; lo = g_w1lo; }
    else if (layer == 1) { Nn = 256; hi = g_w2hi; lo = g_w2lo; }
    else                 { Nn = 32;  hi = g_w3hi; lo = g_w3lo; }
    int idx = blockIdx.x * blockDim.x + threadIdx.x;
    if (idx >= Kd * Nn) return;
    int k = idx / Nn, n = idx % Nn;
    float v = W[idx];
    bf16 h = __float2bfloat16(v);
    hi[n * Kd + k] = h;
    lo[n * Kd + k] = __float2bfloat16(v - __bfloat162float(h));
}

// ---------------- tensor-core GEMM ----------------
__device__ __forceinline__ void mma16816(float* c, const uint32_t* a, const uint32_t* b) {
    asm volatile(
        "mma.sync.aligned.m16n8k16.row.col.f32.bf16.bf16.f32 "
        "{%0,%1,%2,%3}, {%4,%5,%6,%7}, {%8,%9}, {%0,%1,%2,%3};\n"
        : "+f"(c[0]), "+f"(c[1]), "+f"(c[2]), "+f"(c[3])
        : "r"(a[0]), "r"(a[1]), "r"(a[2]), "r"(a[3]), "r"(b[0]), "r"(b[1]));
}

// pack 2 floats -> bf16x2 (round-to-nearest)
__device__ __forceinline__ uint32_t pack_bf2(float a, float b) {
    uint32_t r;
    asm("cvt.rn.bf16x2.f32 %0, %1, %2;" : "=r"(r) : "f"(b), "f"(a));
    return r;
}

// C[M,NOUT] = A_fp32[M,256] @ W[256,NOUT] (+bias, optional relu), fp32 out.
// layer selects device-global operands INSIDE the kernel (never from host).
// Block tile 128 x NT, KC=32, 256 threads, 8 warps. Plain LDG -> register
// carry -> STS, single smem buffer. A split to bf16 hi/lo at STS time;
// products hi*hi + hi*lo + lo*hi fused per chunk.
template <int NT, bool RELU>
__global__ void __launch_bounds__(256)
gemm_kernel(int layer, const float* __restrict__ Ax,
            const float* __restrict__ bias, int M) {
    constexpr int MT   = (NT == 128) ? 4 : 1;
    constexpr int NOUT = (NT == 128) ? 256 : 32;
    __shared__ bf16 Afh[128][40];  // 80 B rows, 16B-aligned stores
    __shared__ bf16 Afl[128][40];
    __shared__ bf16 Bfh[NT][40];
    __shared__ bf16 Bfl[NT][40];

    const float* A;
    const bf16 *Bhi, *Blo;
    float* Out;
    if (layer == 0)      { A = Ax;   Bhi = g_w1hi; Blo = g_w1lo; Out = g_h1; }
    else if (layer == 1) { A = g_h1; Bhi = g_w2hi; Blo = g_w2lo; Out = g_h2; }
    else                 { A = g_h2; Bhi = g_w3hi; Blo = g_w3lo; Out = g_h0; }

    const int tid = threadIdx.x;
    const int warp = tid >> 5, lane = tid & 31;
    const int g = lane >> 2, tg = lane & 3;
    const int wrow = (NT == 128) ? (warp & 1) * 64 : warp * 16;
    const int wcol = (NT == 128) ? (warp >> 1) * 32 : 0;
    const int m0 = blockIdx.x * 128;
    const int n0 = blockIdx.y * NT;

    float acc[MT][4][4];
#pragma unroll
    for (int a = 0; a < MT; a++)
#pragma unroll
        for (int b = 0; b < 4; b++)
#pragma unroll
            for (int c = 0; c < 4; c++) acc[a][b][c] = 0.f;

    // register carry for one KC=32 chunk
    float4 ra[4];           // A: 128x32 fp32 -> 4 float4/thread
    uint4  rbh[2], rbl[2];  // B: NT x 32 bf16 per seg

    // ---- prologue: load chunk 0 ----
#pragma unroll
    for (int i = 0; i < 4; i++) {
        int id = i * 256 + tid;
        int r = id >> 3, c4 = (id & 7) << 2;
        int row = m0 + r; if (row >= M) row = M - 1;
        ra[i] = *(const float4*)(A + (size_t)row * 256 + c4);
    }
    if (NT == 128) {
#pragma unroll
        for (int i = 0; i < 2; i++) {
            int id = i * 256 + tid;
            int r = id >> 2, c8 = (id & 3) << 3;
            rbh[i] = *(const uint4*)(Bhi + (size_t)(n0 + r) * 256 + c8);
            rbl[i] = *(const uint4*)(Blo + (size_t)(n0 + r) * 256 + c8);
        }
    } else if (tid < 128) {
        int r = tid >> 2, c8 = (tid & 3) << 3;
        rbh[0] = *(const uint4*)(Bhi + (size_t)(n0 + r) * 256 + c8);
        rbl[0] = *(const uint4*)(Blo + (size_t)(n0 + r) * 256 + c8);
    }

#pragma unroll 1
    for (int k = 0; k < 8; k++) {
        __syncthreads();  // previous chunk's compute done
        // ---- STS current chunk (A split to hi/lo at store time) ----
#pragma unroll
        for (int i = 0; i < 4; i++) {
            int id = i * 256 + tid;
            int r = id >> 3, c4 = (id & 7) << 2;
            float4 v = ra[i];
            uint2 uh, ul;
            uh.x = pack_bf2(v.x, v.y);
            uh.y = pack_bf2(v.z, v.w);
            float h0 = __bfloat162float(__float2bfloat16(v.x));
            float h1 = __bfloat162float(__float2bfloat16(v.y));
            float h2 = __bfloat162float(__float2bfloat16(v.z));
            float h3 = __bfloat162float(__float2bfloat16(v.w));
            ul.x = pack_bf2(v.x - h0, v.y - h1);
            ul.y = pack_bf2(v.z - h2, v.w - h3);
            *(uint2*)&Afh[r][c4] = uh;
            *(uint2*)&Afl[r][c4] = ul;
        }
        if (NT == 128) {
#pragma unroll
            for (int i = 0; i < 2; i++) {
                int id = i * 256 + tid;
                int r = id >> 2, c8 = (id & 3) << 3;
                *(uint4*)&Bfh[r][c8] = rbh[i];
                *(uint4*)&Bfl[r][c8] = rbl[i];
            }
        } else if (tid < 128) {
            int r = tid >> 2, c8 = (tid & 3) << 3;
            *(uint4*)&Bfh[r][c8] = rbh[0];
            *(uint4*)&Bfl[r][c8] = rbl[0];
        }
        __syncthreads();

        // ---- prefetch next chunk into registers (overlaps MMA below) ----
        if (k < 7) {
            const int kc = (k + 1) * 32;
#pragma unroll
            for (int i = 0; i < 4; i++) {
                int id = i * 256 + tid;
                int r = id >> 3, c4 = (id & 7) << 2;
                int row = m0 + r; if (row >= M) row = M - 1;
                ra[i] = *(const float4*)(A + (size_t)row * 256 + kc + c4);
            }
            if (NT == 128) {
#pragma unroll
                for (int i = 0; i < 2; i++) {
                    int id = i * 256 + tid;
                    int r = id >> 2, c8 = (id & 3) << 3;
                    rbh[i] = *(const uint4*)(Bhi + (size_t)(n0 + r) * 256 + kc + c8);
                    rbl[i] = *(const uint4*)(Blo + (size_t)(n0 + r) * 256 + kc + c8);
                }
            } else if (tid < 128) {
                int r = tid >> 2, c8 = (tid & 3) << 3;
                rbh[0] = *(const uint4*)(Bhi + (size_t)(n0 + r) * 256 + kc + c8);
                rbl[0] = *(const uint4*)(Blo + (size_t)(n0 + r) * 256 + kc + c8);
            }
        }

        // ---- compute: 2 k-steps of 16 ----
#pragma unroll
        for (int ks = 0; ks < 32; ks += 16) {
            uint32_t ah[MT][4], al[MT][4];
#pragma unroll
            for (int mt = 0; mt < MT; mt++) {
#pragma unroll
                for (int f = 0; f < 4; f++) {
                    int rr = wrow + mt * 16 + g + ((f & 1) ? 8 : 0);
                    int cc = ks + 2 * tg + ((f & 2) ? 8 : 0);
                    ah[mt][f] = *(const uint32_t*)&Afh[rr][cc];
                    al[mt][f] = *(const uint32_t*)&Afl[rr][cc];
                }
            }
#pragma unroll
            for (int nt = 0; nt < 4; nt++) {
                int cb = wcol + nt * 8 + g;
                uint32_t bh[2], bl[2];
                bh[0] = *(const uint32_t*)&Bfh[cb][ks + 2 * tg];
                bh[1] = *(const uint32_t*)&Bfh[cb][ks + 2 * tg + 8];
                bl[0] = *(const uint32_t*)&Bfl[cb][ks + 2 * tg];
                bl[1] = *(const uint32_t*)&Bfl[cb][ks + 2 * tg + 8];
#pragma unroll
                for (int mt = 0; mt < MT; mt++) {
                    mma16816(acc[mt][nt], ah[mt], bh);  // hi*hi
                    mma16816(acc[mt][nt], ah[mt], bl);  // hi*lo
                    mma16816(acc[mt][nt], al[mt], bh);  // lo*hi
                }
            }
        }
    }

    // ---- epilogue: bias (+relu), fp32 out ----
#pragma unroll
    for (int mt = 0; mt < MT; mt++) {
        int r0 = m0 + wrow + mt * 16 + g;
#pragma unroll
        for (int nt = 0; nt < 4; nt++) {
            int c0 = n0 + wcol + nt * 8 + 2 * tg;
            float b0v = bias[c0], b1v = bias[c0 + 1];
            float v00 = acc[mt][nt][0] + b0v;
            float v01 = acc[mt][nt][1] + b1v;
            float v10 = acc[mt][nt][2] + b0v;
            float v11 = acc[mt][nt][3] + b1v;
            if (RELU) {
                v00 = fmaxf(v00, 0.f); v01 = fmaxf(v01, 0.f);
                v10 = fmaxf(v10, 0.f); v11 = fmaxf(v11, 0.f);
            }
            if (r0 < M)     *(float2*)(Out + (size_t)r0 * NOUT + c0) = make_float2(v00, v01);
            if (r0 + 8 < M) *(float2*)(Out + (size_t)(r0 + 8) * NOUT + c0) = make_float2(v10, v11);
        }
    }
}

// ---------------- graph normalization + CSR build ----------------
__global__ void deg_init_kernel() {
    int i = blockIdx.x * blockDim.x + threadIdx.x;
    if (i < N_NODES) { g_deg[i] = 1; g_cursor[i] = 0; }  // self-loop included
}

__global__ void deg_count_kernel(const void* __restrict__ ei) {
    int e = blockIdx.x * blockDim.x + threadIdx.x;
    if (e >= E_EDGES) return;
    int d;
    if (g_is64) d = (int)((const long long*)ei)[E_EDGES + e];
    else        d = ((const int*)ei)[E_EDGES + e];
    atomicAdd(&g_deg[d], 1);
}

__global__ void dinv_kernel() {
    int i = blockIdx.x * blockDim.x + threadIdx.x;
    if (i < N_NODES) g_dinv[i] = rsqrtf((float)g_deg[i]);
}

// single-block exclusive scan of (deg[i]-1) -> g_start
__global__ void scan_kernel() {
    __shared__ int ssum[1024];
    const int t = threadIdx.x;
    const int CH = (N_NODES + 1023) / 1024;
    int begin = t * CH;
    int end = begin + CH; if (end > N_NODES) end = N_NODES;
    int s = 0;
    for (int i = begin; i < end && i < N_NODES; i++) s += g_deg[i] - 1;
    ssum[t] = s;
    __syncthreads();
    for (int off = 1; off < 1024; off <<= 1) {
        int v = (t >= off) ? ssum[t - off] : 0;
        __syncthreads();
        ssum[t] += v;
        __syncthreads();
    }
    int run = (t == 0) ? 0 : ssum[t - 1];
    for (int i = begin; i < end && i < N_NODES; i++) {
        g_start[i] = run;
        run += g_deg[i] - 1;
    }
    if (t == 1023) g_start[N_NODES] = run;
}

__global__ void scatter_kernel(const void* __restrict__ ei) {
    int e = blockIdx.x * blockDim.x + threadIdx.x;
    if (e >= E_EDGES) return;
    int s, d;
    if (g_is64) {
        const long long* p = (const long long*)ei;
        s = (int)p[e]; d = (int)p[E_EDGES + e];
    } else {
        const int* p = (const int*)ei;
        s = p[e]; d = p[E_EDGES + e];
    }
    int pos = g_start[d] + atomicAdd(&g_cursor[d], 1);
    g_esrc[pos] = s;
    g_ew[pos] = g_dinv[s] * g_dinv[d];
}

// ---------------- fused propagation round (gather, no atomics) ----------------
__global__ void prop_kernel(int round, float* __restrict__ dout) {
    const float* hin = (round == 0) ? g_h0 : g_hbuf;
    float* hout = (round == 0) ? g_hbuf : dout;
    int gid = blockIdx.x * blockDim.x + threadIdx.x;
    int node = gid >> 3;
    int sub = gid & 7;
    if (node >= N_NODES) return;
    const float4* hin4 = (const float4*)hin;
    int s = g_start[node];
    int e = g_start[node + 1];
    float4 acc = make_float4(0.f, 0.f, 0.f, 0.f);
    for (int j = s; j < e; j++) {
        int src = g_esrc[j];
        float w = g_ew[j];
        float4 hv = hin4[src * 8 + sub];
        acc.x += w * hv.x; acc.y += w * hv.y;
        acc.z += w * hv.z; acc.w += w * hv.w;
    }
    float di = g_dinv[node];
    float sw = di * di;
    float4 hs = hin4[node * 8 + sub];
    float4 h0v = ((const float4*)g_h0)[node * 8 + sub];
    float4 o;
    o.x = 0.9f * (acc.x + sw * hs.x) + 0.1f * h0v.x;
    o.y = 0.9f * (acc.y + sw * hs.y) + 0.1f * h0v.y;
    o.z = 0.9f * (acc.z + sw * hs.z) + 0.1f * h0v.z;
    o.w = 0.9f * (acc.w + sw * hs.w) + 0.1f * h0v.w;
    ((float4*)hout)[node * 8 + sub] = o;
}

// ---------------- launch ----------------
extern "C" void kernel_launch(void* const* d_in, const int* in_sizes, int n_in,
                              void* d_out, int out_size) {
    const float* x     = (const float*)d_in[0];
    const void*  ei    = d_in[1];
    const float* W_in  = (const float*)d_in[2];
    const float* b_in  = (const float*)d_in[3];
    const float* W_h   = (const float*)d_in[4];
    const float* b_h   = (const float*)d_in[5];
    const float* W_out = (const float*)d_in[6];
    const float* b_out = (const float*)d_in[7];
    float* out = (float*)d_out;

    detect_kernel<<<1, 256>>>((const int*)ei);

    split_w_kernel<<<(C_IN * C_HID + 255) / 256, 256>>>(0, W_in);
    split_w_kernel<<<(C_HID * C_HID + 255) / 256, 256>>>(1, W_h);
    split_w_kernel<<<(C_HID * C_OUT + 255) / 256, 256>>>(2, W_out);

    // CSR build (independent of GEMMs)
    deg_init_kernel<<<(N_NODES + 255) / 256, 256>>>();
    deg_count_kernel<<<(E_EDGES + 255) / 256, 256>>>(ei);
    dinv_kernel<<<(N_NODES + 255) / 256, 256>>>();
    scan_kernel<<<1, 1024>>>();
    scatter_kernel<<<(E_EDGES + 255) / 256, 256>>>(ei);

    const int MB = (N_NODES + 127) / 128;  // 782
    gemm_kernel<128, true><<<dim3(MB, 2), 256>>>(0, x, b_in, N_NODES);
    gemm_kernel<128, true><<<dim3(MB, 2), 256>>>(1, x, b_h, N_NODES);
    gemm_kernel<32, false><<<dim3(MB, 1), 256>>>(2, x, b_out, N_NODES);

    const int PB = (N_NODES * 8 + 255) / 256;
    prop_kernel<<<PB, 256>>>(0, out);
    prop_kernel<<<PB, 256>>>(1, out);
}